// round 7
// baseline (speedup 1.0000x reference)
#include <cuda_runtime.h>
#include <cuda_fp16.h>
#include <cstdint>

// VQ: B=16, N=4096, D=128, M=2048
// out layout (float32): quantized_st[8388608], loss[1], perp[1], indices[65536]

#define BN_TOTAL 65536
#define M_CB     2048
#define D_DIM    128
#define Q_ELEMS  8388608
#define LOSS_OFF 8388608
#define PERP_OFF 8388609
#define IDX_OFF  8388610

#define ROW_PITCH   272u                 // 136 fp16 per row (128 data + 8 pad)
#define SPLIT_BYTES (M_CB * ROW_PITCH)   // 557056 per split image
#define A_SPLIT     34816u               // 128 rows * 272
#define B_SPLIT     17408u               // 64 rows * 272
#define B_BUF       34816u               // 2 splits (hi, mid)
#define NUM_NT      32

#define THRESH      2.0e-3f              // ~4x the rigorous approx-dist error bound

// SMEM map (bytes)
#define SM_A      0u                     // 2 splits * 34816 = 69632
#define SM_B      69632u                 // 3 bufs * 34816 = 104448
#define SM_L2K    174080u                // 8192
#define SM_L2Q    182272u                // 512
#define SM_CANDV  182784u                // 128*8*4 = 4096
#define SM_CANDI  186880u                // 4096
#define SM_BEST   190976u                // 512
#define SM_WSUM   191488u                // 64
#define SM_TOTAL  191552u

__device__ float g_l2k[M_CB];
__device__ int   g_counts[M_CB];
__device__ float g_loss;
__device__ __align__(256) unsigned char g_wsplit[2u * SPLIT_BYTES];

// ---------------------------------------------------------------------------
__device__ __forceinline__ uint32_t smem_to_u32(const void* p) {
    uint32_t a;
    asm("{ .reg .u64 t; cvta.to.shared.u64 t, %1; cvt.u32.u64 %0, t; }"
        : "=r"(a) : "l"(p));
    return a;
}
__device__ __forceinline__ void cp16(uint32_t dst, const void* src) {
    asm volatile("cp.async.cg.shared.global [%0], [%1], 16;"
                 :: "r"(dst), "l"(src) : "memory");
}
__device__ __forceinline__ void cp_commit() {
    asm volatile("cp.async.commit_group;" ::: "memory");
}
__device__ __forceinline__ void cp_wait1() {
    asm volatile("cp.async.wait_group 1;" ::: "memory");
}
__device__ __forceinline__ void cp_wait0() {
    asm volatile("cp.async.wait_group 0;" ::: "memory");
}
__device__ __forceinline__ void ldsm4(uint32_t* r, uint32_t addr) {
    asm volatile("ldmatrix.sync.aligned.m8n8.x4.shared.b16 {%0,%1,%2,%3}, [%4];"
                 : "=r"(r[0]), "=r"(r[1]), "=r"(r[2]), "=r"(r[3]) : "r"(addr));
}
__device__ __forceinline__ void mma_f16(float* d, const uint32_t* a, const uint32_t* b) {
    asm volatile(
        "mma.sync.aligned.m16n8k16.row.col.f32.f16.f16.f32 "
        "{%0,%1,%2,%3}, {%4,%5,%6,%7}, {%8,%9}, {%0,%1,%2,%3};"
        : "+f"(d[0]), "+f"(d[1]), "+f"(d[2]), "+f"(d[3])
        : "r"(a[0]), "r"(a[1]), "r"(a[2]), "r"(a[3]), "r"(b[0]), "r"(b[1]));
}
__device__ __forceinline__ void split2h(float v, __half& h, __half& m) {
    h = __float2half_rn(v);
    float r1 = __fsub_rn(v, __half2float(h));
    m = __float2half_rn(r1);
}
__device__ __forceinline__ void top2_upd(float v, int ix, float& b1, int& j1,
                                         float& b2, int& j2) {
    if (v < b1)      { b2 = b1; j2 = j1; b1 = v; j1 = ix; }
    else if (v < b2) { b2 = v;  j2 = ix; }
}

// ---------------------------------------------------------------------------
__global__ void noop_kernel() {}

// ---------------------------------------------------------------------------
// prep: codebook hi/mid fp16 splits into padded gmem images + ||k||^2 + zeroing
// grid 128 x 256 (one octet per thread)
// ---------------------------------------------------------------------------
__global__ void prep_kernel(const float* __restrict__ w) {
    const int oct = blockIdx.x * 256 + threadIdx.x;   // 0..32767
    {
        int n = oct >> 4, k0 = (oct & 15) << 3;
        const float* src = w + (size_t)n * D_DIM + k0;
        __align__(16) __half hi[8], mi[8];
#pragma unroll
        for (int j = 0; j < 8; j++) split2h(src[j], hi[j], mi[j]);
        uint32_t off = (uint32_t)n * ROW_PITCH + (uint32_t)k0 * 2;
        *(uint4*)(g_wsplit + off)               = *(uint4*)hi;
        *(uint4*)(g_wsplit + SPLIT_BYTES + off) = *(uint4*)mi;
    }
    if (oct < M_CB) {
        const float* wr = w + (size_t)oct * D_DIM;
        float s = 0.f;
        for (int i = 0; i < D_DIM; i++)
            s = __fadd_rn(s, __fmul_rn(wr[i], wr[i]));   // strict sequential
        g_l2k[oct]    = s;
        g_counts[oct] = 0;
        if (oct == 0) g_loss = 0.f;
    }
}

// ---------------------------------------------------------------------------
__device__ __forceinline__ void load_b(uint32_t sb, int buf, int nt, int tid) {
#pragma unroll
    for (int s = 0; s < 2; s++) {
        const unsigned char* src =
            g_wsplit + (size_t)s * SPLIT_BYTES + (size_t)nt * B_SPLIT;
        uint32_t dst = sb + SM_B + (uint32_t)buf * B_BUF + (uint32_t)s * B_SPLIT;
        for (int i = tid; i < (int)(B_SPLIT / 16); i += 512)
            cp16(dst + (uint32_t)i * 16u, src + (size_t)i * 16);
    }
}

__device__ __forceinline__ float exact_dist(const float* __restrict__ xrow,
                                            const float* __restrict__ w,
                                            int n, float l2q, float l2k) {
    const float4* wr = (const float4*)(w + (size_t)n * D_DIM);
    const float4* xr = (const float4*)xrow;
    float ps = 0.f;
#pragma unroll
    for (int i = 0; i < 32; i++) {
        float4 a = xr[i], b = wr[i];
        ps = __fmaf_rn(a.x, b.x, ps);
        ps = __fmaf_rn(a.y, b.y, ps);
        ps = __fmaf_rn(a.z, b.z, ps);
        ps = __fmaf_rn(a.w, b.w, ps);
    }
    return __fmaf_rn(-2.f, ps, __fadd_rn(l2q, l2k));
}

// ---------------------------------------------------------------------------
// main: M=128 query tile per CTA, 512 threads (16 warps, 4x4 warp grid).
// 3-pass fp16-split HMMA approx sweep with per-thread top-2 argmin tracking;
// tiny exact fp32 refine for near-tie rows; gather/loss/hist epilogue.
// ---------------------------------------------------------------------------
__global__ __launch_bounds__(512, 1)
void vq_main_kernel(const float* __restrict__ x, const float* __restrict__ w,
                    float* __restrict__ out)
{
    extern __shared__ char smem[];
    const uint32_t sb = smem_to_u32(smem);
    const int tid = threadIdx.x;
    const int wid = tid >> 5, l = tid & 31;
    const int wx = wid & 3, wy = wid >> 2;        // wx: M (4), wy: N (4)
    const int lq = l >> 2, lr = l & 3;
    const int m0 = blockIdx.x * 128;

    float* l2k_s  = (float*)(smem + SM_L2K);
    float* l2q_s  = (float*)(smem + SM_L2Q);
    float* candv  = (float*)(smem + SM_CANDV);
    int*   candi  = (int*)  (smem + SM_CANDI);
    int*   best_s = (int*)  (smem + SM_BEST);
    float* wsum   = (float*)(smem + SM_WSUM);

    // ---- build A split images (hi/mid fp16), padded rows
#pragma unroll
    for (int i = 0; i < 4; i++) {
        int idx = tid + (i << 9);               // 0..2047 octets
        int r = idx >> 4, k0 = (idx & 15) << 3;
        const float4* src = (const float4*)(x + (size_t)(m0 + r) * D_DIM + k0);
        float4 v0 = src[0], v1 = src[1];
        float vv[8] = {v0.x, v0.y, v0.z, v0.w, v1.x, v1.y, v1.z, v1.w};
        __align__(16) __half hi[8], mi[8];
#pragma unroll
        for (int j = 0; j < 8; j++) split2h(vv[j], hi[j], mi[j]);
        uint32_t off = SM_A + (uint32_t)r * ROW_PITCH + (uint32_t)k0 * 2;
        *(uint4*)(smem + off)           = *(uint4*)hi;
        *(uint4*)(smem + off + A_SPLIT) = *(uint4*)mi;
    }
    // ---- stage l2k (512 float4 = 2048 floats)
    ((float4*)l2k_s)[tid] = ((const float4*)g_l2k)[tid];
    // ---- l2q per row: strict sequential fp32 (reference rounding)
    if (tid < 128) {
        const float* xr = x + (size_t)(m0 + tid) * D_DIM;
        float s = 0.f;
        for (int k = 0; k < D_DIM; k++)
            s = __fadd_rn(s, __fmul_rn(xr[k], xr[k]));
        l2q_s[tid] = s;
    }

    // prefetch B tiles 0,1 (bufs 0,1 of 3)
    load_b(sb, 0, 0, tid);
    cp_commit();
    load_b(sb, 1, 1, tid);
    cp_commit();

    float lqr[2][2];
    // (valid after first __syncthreads; read below happens post-barrier via regs)
    uint32_t aAddr[2][2];
    {
        uint32_t row = (uint32_t)(wx * 32) + (uint32_t)(l & 7) + (uint32_t)((l >> 3) & 1) * 8u;
        uint32_t kb  = (uint32_t)((l >> 4) & 1) * 16u;
#pragma unroll
        for (int s = 0; s < 2; s++)
#pragma unroll
            for (int mi = 0; mi < 2; mi++)
                aAddr[s][mi] = sb + SM_A + (uint32_t)s * A_SPLIT
                             + (row + (uint32_t)mi * 16u) * ROW_PITCH + kb;
    }
    uint32_t bAddr[2];
    {
        uint32_t row = (uint32_t)(wy * 16) + (uint32_t)(l & 7) + (uint32_t)((l >> 4) & 1) * 8u;
        uint32_t kb  = (uint32_t)((l >> 3) & 1) * 16u;
#pragma unroll
        for (int s = 0; s < 2; s++)
            bAddr[s] = sb + SM_B + (uint32_t)s * B_SPLIT + row * ROW_PITCH + kb;
    }

    // per-thread top-2 per row-slot (4 slots: mi*2 + h)
    float t1v[4], t2v[4];
    int   t1i[4], t2i[4];
#pragma unroll
    for (int s = 0; s < 4; s++) {
        t1v[s] = 3.0e38f; t2v[s] = 3.0e38f;
        t1i[s] = 0x7fffffff; t2i[s] = 0x7fffffff;
    }

    bool first = true;
    for (int nt = 0; nt < NUM_NT; nt++) {
        if (nt < NUM_NT - 1) cp_wait1(); else cp_wait0();   // tile nt arrived
        __syncthreads();    // data visible to all; all warps done with buf (nt-1)%3
        if (first) {
#pragma unroll
            for (int mi = 0; mi < 2; mi++)
#pragma unroll
                for (int h = 0; h < 2; h++)
                    lqr[mi][h] = l2q_s[wx * 32 + mi * 16 + h * 8 + lq];
            first = false;
        }
        if (nt + 2 < NUM_NT) {
            load_b(sb, (nt + 2) % 3, nt + 2, tid);
            cp_commit();
        }

        float acc[2][2][4];
#pragma unroll
        for (int mi = 0; mi < 2; mi++)
#pragma unroll
            for (int ni = 0; ni < 2; ni++)
#pragma unroll
                for (int q = 0; q < 4; q++) acc[mi][ni][q] = 0.f;

        const uint32_t bOff = (uint32_t)(nt % 3) * B_BUF;

#pragma unroll
        for (int c = 0; c < 8; c++) {
            const uint32_t kb = (uint32_t)c * 32u;
            uint32_t aF[2][2][4];
#pragma unroll
            for (int s = 0; s < 2; s++)
#pragma unroll
                for (int mi = 0; mi < 2; mi++)
                    ldsm4(aF[s][mi], aAddr[s][mi] + kb);
            uint32_t bF[2][4];
#pragma unroll
            for (int s = 0; s < 2; s++)
                ldsm4(bF[s], bAddr[s] + bOff + kb);

            // passes: hh, hM, mH
            const int PA[3] = {0, 0, 1};
            const int PB[3] = {0, 1, 0};
#pragma unroll
            for (int p = 0; p < 3; p++)
#pragma unroll
                for (int mi = 0; mi < 2; mi++)
#pragma unroll
                    for (int ni = 0; ni < 2; ni++)
                        mma_f16(acc[mi][ni], aF[PA[p]][mi], &bF[PB[p]][ni * 2]);
        }

        // epilogue: per-thread top-2 update (register-only, ascending index)
#pragma unroll
        for (int mi = 0; mi < 2; mi++)
#pragma unroll
            for (int ni = 0; ni < 2; ni++) {
                const int col0 = nt * 64 + wy * 16 + ni * 8 + (lr << 1);
                const float2 lk = *(const float2*)(l2k_s + col0);
                float v;
                v = __fmaf_rn(-2.f, acc[mi][ni][0], __fadd_rn(lqr[mi][0], lk.x));
                top2_upd(v, col0,     t1v[mi*2],   t1i[mi*2],   t2v[mi*2],   t2i[mi*2]);
                v = __fmaf_rn(-2.f, acc[mi][ni][1], __fadd_rn(lqr[mi][0], lk.y));
                top2_upd(v, col0 + 1, t1v[mi*2],   t1i[mi*2],   t2v[mi*2],   t2i[mi*2]);
                v = __fmaf_rn(-2.f, acc[mi][ni][2], __fadd_rn(lqr[mi][1], lk.x));
                top2_upd(v, col0,     t1v[mi*2+1], t1i[mi*2+1], t2v[mi*2+1], t2i[mi*2+1]);
                v = __fmaf_rn(-2.f, acc[mi][ni][3], __fadd_rn(lqr[mi][1], lk.y));
                top2_upd(v, col0 + 1, t1v[mi*2+1], t1i[mi*2+1], t2v[mi*2+1], t2i[mi*2+1]);
            }
        // no trailing barrier: next iteration's barrier protects buffer reuse
    }

    // ---- merge top-2 across the 4 lanes sharing each row (lr dimension)
#pragma unroll
    for (int s = 0; s < 4; s++) {
        float v1 = t1v[s], v2 = t2v[s];
        int   i1 = t1i[s], i2 = t2i[s];
#pragma unroll
        for (int off = 1; off <= 2; off <<= 1) {
            float u1 = __shfl_xor_sync(0xffffffffu, v1, off);
            int   j1 = __shfl_xor_sync(0xffffffffu, i1, off);
            float u2 = __shfl_xor_sync(0xffffffffu, v2, off);
            int   j2 = __shfl_xor_sync(0xffffffffu, i2, off);
            if (u1 < v1 || (u1 == v1 && j1 < i1)) {
                if (v1 < u2 || (v1 == u2 && i1 < j2)) { v2 = v1; i2 = i1; }
                else                                  { v2 = u2; i2 = j2; }
                v1 = u1; i1 = j1;
            } else {
                if (u1 < v2 || (u1 == v2 && j1 < i2)) { v2 = u1; i2 = j1; }
            }
        }
        if (lr == 0) {
            int mi = s >> 1, h = s & 1;
            int row = wx * 32 + mi * 16 + h * 8 + lq;
            candv[row * 8 + wy * 2 + 0] = v1;
            candv[row * 8 + wy * 2 + 1] = v2;
            candi[row * 8 + wy * 2 + 0] = i1;
            candi[row * 8 + wy * 2 + 1] = i2;
        }
    }
    __syncthreads();

    // ---- per-row final scan + rare exact refine
    if (tid < 128) {
        float b1 = 3.0e38f, b2 = 3.0e38f;
        int   j1 = 0x7fffffff, j2 = 0x7fffffff;
#pragma unroll
        for (int j = 0; j < 8; j++) {
            float v = candv[tid * 8 + j];
            int   ix = candi[tid * 8 + j];
            if (v < b1 || (v == b1 && ix < j1)) { b2 = b1; j2 = j1; b1 = v; j1 = ix; }
            else if (v < b2 || (v == b2 && ix < j2)) { b2 = v; j2 = ix; }
        }
        int best = j1;
        if (b2 - b1 <= THRESH) {
            const float* xrow = x + (size_t)(m0 + tid) * D_DIM;
            const float l2q_r = l2q_s[tid];
            float bd = 3.0e38f;
            int   bi = 0x7fffffff;
            for (int j = 0; j < 8; j++) {
                float v = candv[tid * 8 + j];
                if (v <= b1 + THRESH) {
                    int n = candi[tid * 8 + j];
                    float d = exact_dist(xrow, w, n, l2q_r, l2k_s[n]);
                    if (d < bd || (d == bd && n < bi)) { bd = d; bi = n; }
                }
            }
            best = bi;
        }
        best_s[tid] = best;
        atomicAdd(&g_counts[best], 1);
        out[IDX_OFF + m0 + tid] = (float)best;
    }
    __syncthreads();

    // ---- gather z, quantized_st = x + (z - x), loss partial (quarter-row/thread)
    {
        const int r  = tid >> 2;
        const int kb = (tid & 3) << 5;
        const int best = best_s[r];
        const float4* xr = (const float4*)(x + (size_t)(m0 + r) * D_DIM + kb);
        const float4* wz = (const float4*)(w + (size_t)best * D_DIM + kb);
        float4* oq = (float4*)(out + (size_t)(m0 + r) * D_DIM + kb);
        float lsum = 0.f;
#pragma unroll
        for (int i = 0; i < 8; i++) {
            float4 xv = xr[i], z = wz[i];
            float4 qv;
            qv.x = __fadd_rn(xv.x, __fsub_rn(z.x, xv.x));
            qv.y = __fadd_rn(xv.y, __fsub_rn(z.y, xv.y));
            qv.z = __fadd_rn(xv.z, __fsub_rn(z.z, xv.z));
            qv.w = __fadd_rn(xv.w, __fsub_rn(z.w, xv.w));
            oq[i] = qv;
            float d0 = __fsub_rn(qv.x, xv.x), d1 = __fsub_rn(qv.y, xv.y);
            float d2 = __fsub_rn(qv.z, xv.z), d3 = __fsub_rn(qv.w, xv.w);
            lsum += d0 * d0 + d1 * d1 + d2 * d2 + d3 * d3;
        }
#pragma unroll
        for (int o = 16; o > 0; o >>= 1)
            lsum += __shfl_down_sync(0xffffffffu, lsum, o);
        if ((tid & 31) == 0) wsum[wid] = lsum;
    }
    __syncthreads();
    if (tid == 0) {
        float s = 0.f;
#pragma unroll
        for (int i = 0; i < 16; i++) s += wsum[i];
        atomicAdd(&g_loss, s);
    }
}

// ---------------------------------------------------------------------------
// finalize: loss mean + perplexity
// ---------------------------------------------------------------------------
__global__ void finalize_kernel(float* __restrict__ out) {
    int t = threadIdx.x;
    float s = 0.f;
    for (int i = t; i < M_CB; i += 256) {
        float p = (float)g_counts[i] * (1.0f / 65536.0f);
        s += p * logf(p + 1e-10f);
    }
#pragma unroll
    for (int o = 16; o > 0; o >>= 1)
        s += __shfl_down_sync(0xffffffffu, s, o);
    __shared__ float ws[8];
    if ((t & 31) == 0) ws[t >> 5] = s;
    __syncthreads();
    if (t == 0) {
        float tot = 0.f;
#pragma unroll
        for (int i = 0; i < 8; i++) tot += ws[i];
        out[LOSS_OFF] = g_loss * (1.0f / 8388608.0f);
        out[PERP_OFF] = expf(-tot);
    }
}

// ---------------------------------------------------------------------------
extern "C" void kernel_launch(void* const* d_in, const int* in_sizes, int n_in,
                              void* d_out, int out_size) {
    const float* x = (const float*)d_in[0];
    const float* w = (const float*)d_in[1];
    if (n_in >= 2 && in_sizes[0] == M_CB * D_DIM && in_sizes[1] == Q_ELEMS) {
        x = (const float*)d_in[1];
        w = (const float*)d_in[0];
    }
    float* out = (float*)d_out;

    cudaFuncSetAttribute(vq_main_kernel,
                         cudaFuncAttributeMaxDynamicSharedMemorySize, SM_TOTAL);

    // launch order puts vq_main_kernel at our index 3 (ncu -s 5 with the
    // harness's 2 hidden launches should capture it)
    prep_kernel<<<128, 256>>>(w);
    noop_kernel<<<1, 1>>>();
    noop_kernel<<<1, 1>>>();
    vq_main_kernel<<<BN_TOTAL / 128, 512, SM_TOTAL>>>(x, w, out);
    finalize_kernel<<<1, 256>>>(out);
}

// round 8
// speedup vs baseline: 1.7358x; 1.7358x over previous
#include <cuda_runtime.h>
#include <cuda_fp16.h>
#include <cstdint>

// VQ: B=16, N=4096, D=128, M=2048
// out layout (float32): quantized_st[8388608], loss[1], perp[1], indices[65536]

#define BN_TOTAL 65536
#define M_CB     2048
#define D_DIM    128
#define Q_ELEMS  8388608
#define LOSS_OFF 8388608
#define PERP_OFF 8388609
#define IDX_OFF  8388610

#define ROW_PITCH   272u                 // 136 fp16 per row (128 data + 8 pad)
#define SPLIT_BYTES (M_CB * ROW_PITCH)   // 557056 per split image
#define A_SPLIT     34816u               // 128 rows * 272
#define B_SPLIT     17408u               // 64 rows * 272
#define B_BUF       34816u               // 2 splits (hi, mid)
#define NUM_NT      32

#define THRESH      2.0e-3f              // ~7x the rigorous approx-dist error bound
#define U64MAX      0xFFFFFFFFFFFFFFFFull

// SMEM map (bytes)
#define SM_A      0u                     // 2 splits * 34816 = 69632
#define SM_B      69632u                 // 3 bufs * 34816 = 104448
#define SM_L2K    174080u                // 8192
#define SM_L2Q    182272u                // 512
#define SM_CAND   182784u                // 128 rows * 4 u64 = 4096
#define SM_BEST   186880u                // 512
#define SM_WSUM   187392u                // 64
#define SM_TOTAL  187456u

__device__ float g_l2k[M_CB];
__device__ int   g_counts[M_CB];
__device__ float g_loss;
__device__ __align__(256) unsigned char g_wsplit[2u * SPLIT_BYTES];

// ---------------------------------------------------------------------------
__device__ __forceinline__ uint32_t smem_to_u32(const void* p) {
    uint32_t a;
    asm("{ .reg .u64 t; cvta.to.shared.u64 t, %1; cvt.u32.u64 %0, t; }"
        : "=r"(a) : "l"(p));
    return a;
}
__device__ __forceinline__ void cp16(uint32_t dst, const void* src) {
    asm volatile("cp.async.cg.shared.global [%0], [%1], 16;"
                 :: "r"(dst), "l"(src) : "memory");
}
__device__ __forceinline__ void cp_commit() {
    asm volatile("cp.async.commit_group;" ::: "memory");
}
__device__ __forceinline__ void cp_wait1() {
    asm volatile("cp.async.wait_group 1;" ::: "memory");
}
__device__ __forceinline__ void cp_wait0() {
    asm volatile("cp.async.wait_group 0;" ::: "memory");
}
__device__ __forceinline__ void ldsm4(uint32_t* r, uint32_t addr) {
    asm volatile("ldmatrix.sync.aligned.m8n8.x4.shared.b16 {%0,%1,%2,%3}, [%4];"
                 : "=r"(r[0]), "=r"(r[1]), "=r"(r[2]), "=r"(r[3]) : "r"(addr));
}
__device__ __forceinline__ void mma_f16(float* d, const uint32_t* a, const uint32_t* b) {
    asm volatile(
        "mma.sync.aligned.m16n8k16.row.col.f32.f16.f16.f32 "
        "{%0,%1,%2,%3}, {%4,%5,%6,%7}, {%8,%9}, {%0,%1,%2,%3};"
        : "+f"(d[0]), "+f"(d[1]), "+f"(d[2]), "+f"(d[3])
        : "r"(a[0]), "r"(a[1]), "r"(a[2]), "r"(a[3]), "r"(b[0]), "r"(b[1]));
}
__device__ __forceinline__ void split2h(float v, __half& h, __half& m) {
    h = __float2half_rn(v);
    float r1 = __fsub_rn(v, __half2float(h));
    m = __float2half_rn(r1);
}
// branchless packed top-2: p = (float_bits << 32) | index.
// dists are all >> 0 so unsigned u64 order == (value, index) lexicographic.
__device__ __forceinline__ void t2upd(unsigned long long& b1, unsigned long long& b2,
                                      float v, unsigned n) {
    unsigned long long p =
        ((unsigned long long)__float_as_uint(v) << 32) | (unsigned long long)n;
    unsigned long long mx = p > b1 ? p : b1;
    b1 = p < b1 ? p : b1;
    b2 = mx < b2 ? mx : b2;
}
__device__ __forceinline__ unsigned long long shfl_xor_u64(unsigned long long v, int off) {
    uint32_t lo = (uint32_t)v, hi = (uint32_t)(v >> 32);
    lo = __shfl_xor_sync(0xffffffffu, lo, off);
    hi = __shfl_xor_sync(0xffffffffu, hi, off);
    return ((unsigned long long)hi << 32) | lo;
}

// ---------------------------------------------------------------------------
__global__ void noop_kernel() {}

// ---------------------------------------------------------------------------
// prep: codebook hi/mid fp16 splits into padded gmem images + ||k||^2 + zeroing
// ---------------------------------------------------------------------------
__global__ void prep_kernel(const float* __restrict__ w) {
    const int oct = blockIdx.x * 256 + threadIdx.x;   // 0..32767
    {
        int n = oct >> 4, k0 = (oct & 15) << 3;
        const float* src = w + (size_t)n * D_DIM + k0;
        __align__(16) __half hi[8], mi[8];
#pragma unroll
        for (int j = 0; j < 8; j++) split2h(src[j], hi[j], mi[j]);
        uint32_t off = (uint32_t)n * ROW_PITCH + (uint32_t)k0 * 2;
        *(uint4*)(g_wsplit + off)               = *(uint4*)hi;
        *(uint4*)(g_wsplit + SPLIT_BYTES + off) = *(uint4*)mi;
    }
    if (oct < M_CB) {
        const float* wr = w + (size_t)oct * D_DIM;
        float s = 0.f;
        for (int i = 0; i < D_DIM; i++)
            s = __fadd_rn(s, __fmul_rn(wr[i], wr[i]));   // strict sequential
        g_l2k[oct]    = s;
        g_counts[oct] = 0;
        if (oct == 0) g_loss = 0.f;
    }
}

// ---------------------------------------------------------------------------
__device__ __forceinline__ void load_b(uint32_t sb, int buf, int nt, int tid) {
#pragma unroll
    for (int s = 0; s < 2; s++) {
        const unsigned char* src =
            g_wsplit + (size_t)s * SPLIT_BYTES + (size_t)nt * B_SPLIT;
        uint32_t dst = sb + SM_B + (uint32_t)buf * B_BUF + (uint32_t)s * B_SPLIT;
        for (int i = tid; i < (int)(B_SPLIT / 16); i += 512)
            cp16(dst + (uint32_t)i * 16u, src + (size_t)i * 16);
    }
}

__device__ __forceinline__ float exact_dist(const float* __restrict__ xrow,
                                            const float* __restrict__ w,
                                            int n, float l2q, float l2k) {
    const float4* wr = (const float4*)(w + (size_t)n * D_DIM);
    const float4* xr = (const float4*)xrow;
    float ps = 0.f;
#pragma unroll
    for (int i = 0; i < 32; i++) {
        float4 a = xr[i], b = wr[i];
        ps = __fmaf_rn(a.x, b.x, ps);
        ps = __fmaf_rn(a.y, b.y, ps);
        ps = __fmaf_rn(a.z, b.z, ps);
        ps = __fmaf_rn(a.w, b.w, ps);
    }
    return __fmaf_rn(-2.f, ps, __fadd_rn(l2q, l2k));
}

// ---------------------------------------------------------------------------
// main: M=128 query tile per CTA, 512 threads, warp grid 8(M) x 2(N), mi=1.
// A fragments register-resident across all tiles; 3-pass fp16-split HMMA
// sweep with branchless packed top-2; rare exact fp32 refine; epilogue.
// ---------------------------------------------------------------------------
__global__ __launch_bounds__(512, 1)
void vq_main_kernel(const float* __restrict__ x, const float* __restrict__ w,
                    float* __restrict__ out)
{
    extern __shared__ char smem[];
    const uint32_t sb = smem_to_u32(smem);
    const int tid = threadIdx.x;
    const int wid = tid >> 5, l = tid & 31;
    const int wx = wid & 7, wy = wid >> 3;        // wx: M (8 x 16 rows), wy: N (2 x 32 cols)
    const int lq = l >> 2, lr = l & 3;
    const int m0 = blockIdx.x * 128;

    float* l2k_s  = (float*)(smem + SM_L2K);
    float* l2q_s  = (float*)(smem + SM_L2Q);
    unsigned long long* cand = (unsigned long long*)(smem + SM_CAND);  // [128][4]
    int*   best_s = (int*)  (smem + SM_BEST);
    float* wsum   = (float*)(smem + SM_WSUM);

    // ---- build A split images (hi/mid fp16), padded rows
#pragma unroll
    for (int i = 0; i < 4; i++) {
        int idx = tid + (i << 9);               // 0..2047 octets
        int r = idx >> 4, k0 = (idx & 15) << 3;
        const float4* src = (const float4*)(x + (size_t)(m0 + r) * D_DIM + k0);
        float4 v0 = src[0], v1 = src[1];
        float vv[8] = {v0.x, v0.y, v0.z, v0.w, v1.x, v1.y, v1.z, v1.w};
        __align__(16) __half hi[8], mi[8];
#pragma unroll
        for (int j = 0; j < 8; j++) split2h(vv[j], hi[j], mi[j]);
        uint32_t off = SM_A + (uint32_t)r * ROW_PITCH + (uint32_t)k0 * 2;
        *(uint4*)(smem + off)           = *(uint4*)hi;
        *(uint4*)(smem + off + A_SPLIT) = *(uint4*)mi;
    }
    // ---- stage l2k (512 float4 = 2048 floats)
    ((float4*)l2k_s)[tid] = ((const float4*)g_l2k)[tid];
    // ---- l2q per row: strict sequential fp32 (reference rounding)
    if (tid < 128) {
        const float* xr = x + (size_t)(m0 + tid) * D_DIM;
        float s = 0.f;
        for (int k = 0; k < D_DIM; k++)
            s = __fadd_rn(s, __fmul_rn(xr[k], xr[k]));
        l2q_s[tid] = s;
    }

    // prefetch B tiles 0,1 (bufs 0,1 of 3)
    load_b(sb, 0, 0, tid);
    cp_commit();
    load_b(sb, 1, 1, tid);
    cp_commit();
    cp_wait1();          // B0 complete
    __syncthreads();     // A image, l2q, l2k, B0 visible

    // ---- load A fragments ONCE (register-resident: 2 splits x 8 chunks x 4)
    uint32_t aF[2][8][4];
    {
        uint32_t row = (uint32_t)(wx * 16) + (uint32_t)(l & 15);
        uint32_t kbl = (uint32_t)((l >> 4) & 1) * 16u;
        uint32_t base = sb + SM_A + row * ROW_PITCH + kbl;
#pragma unroll
        for (int s = 0; s < 2; s++)
#pragma unroll
            for (int c = 0; c < 8; c++)
                ldsm4(aF[s][c], base + (uint32_t)s * A_SPLIT + (uint32_t)c * 32u);
    }
    float lqr[2];
    lqr[0] = l2q_s[wx * 16 + lq];
    lqr[1] = l2q_s[wx * 16 + lq + 8];

    // B lane base (per split, per ni16 group); buf offset added per tile
    uint32_t bBase;
    {
        uint32_t row = (uint32_t)(wy * 32) + (uint32_t)(l & 7) + (uint32_t)((l >> 4) & 1) * 8u;
        uint32_t kbl = (uint32_t)((l >> 3) & 1) * 16u;
        bBase = sb + SM_B + row * ROW_PITCH + kbl;
    }

    unsigned long long t1[2] = {U64MAX, U64MAX};
    unsigned long long t2[2] = {U64MAX, U64MAX};

    for (int nt = 0; nt < NUM_NT; nt++) {
        if (nt > 0) {
            if (nt < NUM_NT - 1) cp_wait1(); else cp_wait0();   // tile nt arrived
            __syncthreads();    // all warps done with buf (nt-1)%3
        }
        if (nt + 2 < NUM_NT) {
            load_b(sb, (nt + 2) % 3, nt + 2, tid);
            cp_commit();
        }

        float acc[4][4];
#pragma unroll
        for (int n8 = 0; n8 < 4; n8++)
#pragma unroll
            for (int q = 0; q < 4; q++) acc[n8][q] = 0.f;

        const uint32_t bOff = (uint32_t)(nt % 3) * B_BUF;

#pragma unroll
        for (int c = 0; c < 8; c++) {
            const uint32_t kb = (uint32_t)c * 32u;
            uint32_t bF[2][2][4];    // [split][ni16][reg]
#pragma unroll
            for (int s = 0; s < 2; s++)
#pragma unroll
                for (int g = 0; g < 2; g++)
                    ldsm4(bF[s][g],
                          bBase + bOff + (uint32_t)s * B_SPLIT
                                + (uint32_t)g * (16u * ROW_PITCH) + kb);

            // passes: hh, hM, mH
            const int PA[3] = {0, 0, 1};
            const int PB[3] = {0, 1, 0};
#pragma unroll
            for (int p = 0; p < 3; p++)
#pragma unroll
                for (int n8 = 0; n8 < 4; n8++)
                    mma_f16(acc[n8], aF[PA[p]][c], &bF[PB[p]][n8 >> 1][(n8 & 1) * 2]);
        }

        // epilogue: branchless packed top-2 (ascending index order)
#pragma unroll
        for (int n8 = 0; n8 < 4; n8++) {
            const int col0 = nt * 64 + wy * 32 + n8 * 8 + (lr << 1);
            const float2 lk = *(const float2*)(l2k_s + col0);
            float v;
            v = __fmaf_rn(-2.f, acc[n8][0], __fadd_rn(lqr[0], lk.x));
            t2upd(t1[0], t2[0], v, (unsigned)col0);
            v = __fmaf_rn(-2.f, acc[n8][1], __fadd_rn(lqr[0], lk.y));
            t2upd(t1[0], t2[0], v, (unsigned)(col0 + 1));
            v = __fmaf_rn(-2.f, acc[n8][2], __fadd_rn(lqr[1], lk.x));
            t2upd(t1[1], t2[1], v, (unsigned)col0);
            v = __fmaf_rn(-2.f, acc[n8][3], __fadd_rn(lqr[1], lk.y));
            t2upd(t1[1], t2[1], v, (unsigned)(col0 + 1));
        }
        // no trailing barrier: next iteration's barrier protects buffer reuse
    }

    // ---- merge top-2 across the 4 lanes (lr) sharing each row
#pragma unroll
    for (int h = 0; h < 2; h++) {
        unsigned long long b1 = t1[h], b2 = t2[h];
#pragma unroll
        for (int off = 1; off <= 2; off <<= 1) {
            unsigned long long o1 = shfl_xor_u64(b1, off);
            unsigned long long o2 = shfl_xor_u64(b2, off);
            unsigned long long mx = b1 > o1 ? b1 : o1;
            b1 = b1 < o1 ? b1 : o1;
            unsigned long long mn2 = b2 < o2 ? b2 : o2;
            b2 = mn2 < mx ? mn2 : mx;
        }
        if (lr == 0) {
            int row = wx * 16 + h * 8 + lq;
            cand[row * 4 + wy * 2 + 0] = b1;
            cand[row * 4 + wy * 2 + 1] = b2;
        }
    }
    __syncthreads();

    // ---- per-row final scan + rare exact refine
    if (tid < 128) {
        unsigned long long b1 = U64MAX, b2 = U64MAX;
#pragma unroll
        for (int j = 0; j < 4; j++) {
            unsigned long long p = cand[tid * 4 + j];
            unsigned long long mx = p > b1 ? p : b1;
            b1 = p < b1 ? p : b1;
            b2 = mx < b2 ? mx : b2;
        }
        float v1 = __uint_as_float((uint32_t)(b1 >> 32));
        float v2 = __uint_as_float((uint32_t)(b2 >> 32));
        int best = (int)(uint32_t)(b1 & 0xFFFFFFFFu);
        if (v2 - v1 <= THRESH) {
            const float* xrow = x + (size_t)(m0 + tid) * D_DIM;
            const float l2q_r = l2q_s[tid];
            float bd = 3.0e38f;
            int   bi = 0x7fffffff;
#pragma unroll
            for (int j = 0; j < 4; j++) {
                unsigned long long p = cand[tid * 4 + j];
                float pv = __uint_as_float((uint32_t)(p >> 32));
                if (pv <= v1 + THRESH) {
                    int n = (int)(uint32_t)(p & 0xFFFFFFFFu);
                    float d = exact_dist(xrow, w, n, l2q_r, l2k_s[n]);
                    if (d < bd || (d == bd && n < bi)) { bd = d; bi = n; }
                }
            }
            best = bi;
        }
        best_s[tid] = best;
        atomicAdd(&g_counts[best], 1);
        out[IDX_OFF + m0 + tid] = (float)best;
    }
    __syncthreads();

    // ---- gather z, quantized_st = x + (z - x), loss partial (quarter-row/thread)
    {
        const int r  = tid >> 2;
        const int kb = (tid & 3) << 5;
        const int best = best_s[r];
        const float4* xr = (const float4*)(x + (size_t)(m0 + r) * D_DIM + kb);
        const float4* wz = (const float4*)(w + (size_t)best * D_DIM + kb);
        float4* oq = (float4*)(out + (size_t)(m0 + r) * D_DIM + kb);
        float lsum = 0.f;
#pragma unroll
        for (int i = 0; i < 8; i++) {
            float4 xv = xr[i], z = wz[i];
            float4 qv;
            qv.x = __fadd_rn(xv.x, __fsub_rn(z.x, xv.x));
            qv.y = __fadd_rn(xv.y, __fsub_rn(z.y, xv.y));
            qv.z = __fadd_rn(xv.z, __fsub_rn(z.z, xv.z));
            qv.w = __fadd_rn(xv.w, __fsub_rn(z.w, xv.w));
            oq[i] = qv;
            float d0 = __fsub_rn(qv.x, xv.x), d1 = __fsub_rn(qv.y, xv.y);
            float d2 = __fsub_rn(qv.z, xv.z), d3 = __fsub_rn(qv.w, xv.w);
            lsum += d0 * d0 + d1 * d1 + d2 * d2 + d3 * d3;
        }
#pragma unroll
        for (int o = 16; o > 0; o >>= 1)
            lsum += __shfl_down_sync(0xffffffffu, lsum, o);
        if ((tid & 31) == 0) wsum[wid] = lsum;
    }
    __syncthreads();
    if (tid == 0) {
        float s = 0.f;
#pragma unroll
        for (int i = 0; i < 16; i++) s += wsum[i];
        atomicAdd(&g_loss, s);
    }
}

// ---------------------------------------------------------------------------
// finalize: loss mean + perplexity
// ---------------------------------------------------------------------------
__global__ void finalize_kernel(float* __restrict__ out) {
    int t = threadIdx.x;
    float s = 0.f;
    for (int i = t; i < M_CB; i += 256) {
        float p = (float)g_counts[i] * (1.0f / 65536.0f);
        s += p * logf(p + 1e-10f);
    }
#pragma unroll
    for (int o = 16; o > 0; o >>= 1)
        s += __shfl_down_sync(0xffffffffu, s, o);
    __shared__ float ws[8];
    if ((t & 31) == 0) ws[t >> 5] = s;
    __syncthreads();
    if (t == 0) {
        float tot = 0.f;
#pragma unroll
        for (int i = 0; i < 8; i++) tot += ws[i];
        out[LOSS_OFF] = g_loss * (1.0f / 8388608.0f);
        out[PERP_OFF] = expf(-tot);
    }
}

// ---------------------------------------------------------------------------
extern "C" void kernel_launch(void* const* d_in, const int* in_sizes, int n_in,
                              void* d_out, int out_size) {
    const float* x = (const float*)d_in[0];
    const float* w = (const float*)d_in[1];
    if (n_in >= 2 && in_sizes[0] == M_CB * D_DIM && in_sizes[1] == Q_ELEMS) {
        x = (const float*)d_in[1];
        w = (const float*)d_in[0];
    }
    float* out = (float*)d_out;

    cudaFuncSetAttribute(vq_main_kernel,
                         cudaFuncAttributeMaxDynamicSharedMemorySize, SM_TOTAL);

    // same launch order that successfully profiled vq_main last round
    prep_kernel<<<128, 256>>>(w);
    noop_kernel<<<1, 1>>>();
    noop_kernel<<<1, 1>>>();
    vq_main_kernel<<<BN_TOTAL / 128, 512, SM_TOTAL>>>(x, w, out);
    finalize_kernel<<<1, 256>>>(out);
}

// round 10
// speedup vs baseline: 2.1346x; 1.2297x over previous
#include <cuda_runtime.h>
#include <cuda_fp16.h>
#include <cstdint>

// VQ: B=16, N=4096, D=128, M=2048
// out layout (float32): quantized_st[8388608], loss[1], perp[1], indices[65536]

#define BN_TOTAL 65536
#define M_CB     2048
#define D_DIM    128
#define Q_ELEMS  8388608
#define LOSS_OFF 8388608
#define PERP_OFF 8388609
#define IDX_OFF  8388610

#define ROW_PITCH   272u                 // 136 fp16 per row (128 data + 8 pad)
#define SPLIT_BYTES (M_CB * ROW_PITCH)   // 557056 per split image
#define A_SPLIT     17408u               // 64 rows * 272 (per split)
#define B_SPLIT     17408u               // 64 rows * 272
#define B_BUF       34816u               // 2 splits (hi, mid)
#define NUM_NT      32

#define THRESH      2.0e-3f              // ~7x the rigorous approx-dist error bound
#define U64MAX      0xFFFFFFFFFFFFFFFFull

// SMEM map (bytes). A staging image OVERLAYS B buf0 (same 34816 size):
// A is consumed into registers before the first B load lands.
#define SM_AB     0u                     // 2 B bufs * 34816 = 69632 (buf0 = A image first)
#define SM_L2K    69632u                 // 8192
#define SM_L2Q    77824u                 // 256
#define SM_CAND   78080u                 // 64 rows * 4 u64 = 2048
#define SM_BEST   80128u                 // 256
#define SM_WSUM   80384u                 // 32
#define SM_TOTAL  80416u

__device__ float g_l2k[M_CB];
__device__ int   g_counts[M_CB];
__device__ float g_loss;
__device__ __align__(256) unsigned char g_wsplit[2u * SPLIT_BYTES];

// ---------------------------------------------------------------------------
__device__ __forceinline__ uint32_t smem_to_u32(const void* p) {
    uint32_t a;
    asm("{ .reg .u64 t; cvta.to.shared.u64 t, %1; cvt.u32.u64 %0, t; }"
        : "=r"(a) : "l"(p));
    return a;
}
__device__ __forceinline__ void cp16(uint32_t dst, const void* src) {
    asm volatile("cp.async.cg.shared.global [%0], [%1], 16;"
                 :: "r"(dst), "l"(src) : "memory");
}
__device__ __forceinline__ void cp_commit() {
    asm volatile("cp.async.commit_group;" ::: "memory");
}
__device__ __forceinline__ void cp_wait0() {
    asm volatile("cp.async.wait_group 0;" ::: "memory");
}
__device__ __forceinline__ void ldsm4(uint32_t* r, uint32_t addr) {
    asm volatile("ldmatrix.sync.aligned.m8n8.x4.shared.b16 {%0,%1,%2,%3}, [%4];"
                 : "=r"(r[0]), "=r"(r[1]), "=r"(r[2]), "=r"(r[3]) : "r"(addr));
}
__device__ __forceinline__ void mma_f16(float* d, const uint32_t* a, const uint32_t* b) {
    asm volatile(
        "mma.sync.aligned.m16n8k16.row.col.f32.f16.f16.f32 "
        "{%0,%1,%2,%3}, {%4,%5,%6,%7}, {%8,%9}, {%0,%1,%2,%3};"
        : "+f"(d[0]), "+f"(d[1]), "+f"(d[2]), "+f"(d[3])
        : "r"(a[0]), "r"(a[1]), "r"(a[2]), "r"(a[3]), "r"(b[0]), "r"(b[1]));
}
__device__ __forceinline__ void split2h(float v, __half& h, __half& m) {
    h = __float2half_rn(v);
    float r1 = __fsub_rn(v, __half2float(h));
    m = __float2half_rn(r1);
}
// branchless packed top-2: p = (float_bits << 32) | index.
// dists are all >> 0 so unsigned u64 order == (value, index) lexicographic.
__device__ __forceinline__ void t2upd(unsigned long long& b1, unsigned long long& b2,
                                      float v, unsigned n) {
    unsigned long long p =
        ((unsigned long long)__float_as_uint(v) << 32) | (unsigned long long)n;
    unsigned long long mx = p > b1 ? p : b1;
    b1 = p < b1 ? p : b1;
    b2 = mx < b2 ? mx : b2;
}
__device__ __forceinline__ unsigned long long shfl_xor_u64(unsigned long long v, int off) {
    uint32_t lo = (uint32_t)v, hi = (uint32_t)(v >> 32);
    lo = __shfl_xor_sync(0xffffffffu, lo, off);
    hi = __shfl_xor_sync(0xffffffffu, hi, off);
    return ((unsigned long long)hi << 32) | lo;
}

// ---------------------------------------------------------------------------
__global__ void noop_kernel() {}

// ---------------------------------------------------------------------------
// prep: codebook hi/mid fp16 splits into padded gmem images + ||k||^2 + zeroing
// ---------------------------------------------------------------------------
__global__ void prep_kernel(const float* __restrict__ w) {
    const int oct = blockIdx.x * 256 + threadIdx.x;   // 0..32767
    {
        int n = oct >> 4, k0 = (oct & 15) << 3;
        const float* src = w + (size_t)n * D_DIM + k0;
        __align__(16) __half hi[8], mi[8];
#pragma unroll
        for (int j = 0; j < 8; j++) split2h(src[j], hi[j], mi[j]);
        uint32_t off = (uint32_t)n * ROW_PITCH + (uint32_t)k0 * 2;
        *(uint4*)(g_wsplit + off)               = *(uint4*)hi;
        *(uint4*)(g_wsplit + SPLIT_BYTES + off) = *(uint4*)mi;
    }
    if (oct < M_CB) {
        const float* wr = w + (size_t)oct * D_DIM;
        float s = 0.f;
        for (int i = 0; i < D_DIM; i++)
            s = __fadd_rn(s, __fmul_rn(wr[i], wr[i]));   // strict sequential
        g_l2k[oct]    = s;
        g_counts[oct] = 0;
        if (oct == 0) g_loss = 0.f;
    }
}

// ---------------------------------------------------------------------------
__device__ __forceinline__ void load_b(uint32_t sb, int buf, int nt, int tid) {
#pragma unroll
    for (int s = 0; s < 2; s++) {
        const unsigned char* src =
            g_wsplit + (size_t)s * SPLIT_BYTES + (size_t)nt * B_SPLIT;
        uint32_t dst = sb + SM_AB + (uint32_t)buf * B_BUF + (uint32_t)s * B_SPLIT;
        for (int i = tid; i < (int)(B_SPLIT / 16); i += 256)
            cp16(dst + (uint32_t)i * 16u, src + (size_t)i * 16);
    }
}

__device__ __forceinline__ float exact_dist(const float* __restrict__ xrow,
                                            const float* __restrict__ w,
                                            int n, float l2q, float l2k) {
    const float4* wr = (const float4*)(w + (size_t)n * D_DIM);
    const float4* xr = (const float4*)xrow;
    float ps = 0.f;
#pragma unroll
    for (int i = 0; i < 32; i++) {
        float4 a = xr[i], b = wr[i];
        ps = __fmaf_rn(a.x, b.x, ps);
        ps = __fmaf_rn(a.y, b.y, ps);
        ps = __fmaf_rn(a.z, b.z, ps);
        ps = __fmaf_rn(a.w, b.w, ps);
    }
    return __fmaf_rn(-2.f, ps, __fadd_rn(l2q, l2k));
}

// ---------------------------------------------------------------------------
// main: M=64 query tile per CTA, 256 threads (8 warps, 4(M) x 2(N)),
// 2 CTAs/SM. A fragments register-resident; 3-pass fp16-split HMMA sweep
// with branchless packed top-2; rare exact fp32 refine; epilogue.
// ---------------------------------------------------------------------------
__global__ __launch_bounds__(256, 2)
void vq_main_kernel(const float* __restrict__ x, const float* __restrict__ w,
                    float* __restrict__ out)
{
    extern __shared__ char smem[];
    const uint32_t sb = smem_to_u32(smem);
    const int tid = threadIdx.x;
    const int wid = tid >> 5, l = tid & 31;
    const int wx = wid & 3, wy = wid >> 2;        // wx: M (4 x 16 rows), wy: N (2 x 32 cols)
    const int lq = l >> 2, lr = l & 3;
    const int m0 = blockIdx.x * 64;

    float* l2k_s  = (float*)(smem + SM_L2K);
    float* l2q_s  = (float*)(smem + SM_L2Q);
    unsigned long long* cand = (unsigned long long*)(smem + SM_CAND);  // [64][4]
    int*   best_s = (int*)  (smem + SM_BEST);
    float* wsum   = (float*)(smem + SM_WSUM);

    // ---- build A split images (hi/mid fp16) in B-buf0 region (overlay)
#pragma unroll
    for (int i = 0; i < 4; i++) {
        int idx = tid + (i << 8);               // 0..1023 octets (64 rows x 16)
        int r = idx >> 4, k0 = (idx & 15) << 3;
        const float4* src = (const float4*)(x + (size_t)(m0 + r) * D_DIM + k0);
        float4 v0 = src[0], v1 = src[1];
        float vv[8] = {v0.x, v0.y, v0.z, v0.w, v1.x, v1.y, v1.z, v1.w};
        __align__(16) __half hi[8], mi[8];
#pragma unroll
        for (int j = 0; j < 8; j++) split2h(vv[j], hi[j], mi[j]);
        uint32_t off = SM_AB + (uint32_t)r * ROW_PITCH + (uint32_t)k0 * 2;
        *(uint4*)(smem + off)           = *(uint4*)hi;
        *(uint4*)(smem + off + A_SPLIT) = *(uint4*)mi;
    }
    // ---- stage l2k (512 float4 = 2048 floats)
    ((float4*)l2k_s)[tid]       = ((const float4*)g_l2k)[tid];
    ((float4*)l2k_s)[tid + 256] = ((const float4*)g_l2k)[tid + 256];
    // ---- l2q per row: strict sequential fp32 (reference rounding)
    if (tid < 64) {
        const float* xr = x + (size_t)(m0 + tid) * D_DIM;
        float s = 0.f;
        for (int k = 0; k < D_DIM; k++)
            s = __fadd_rn(s, __fmul_rn(xr[k], xr[k]));
        l2q_s[tid] = s;
    }
    __syncthreads();     // A image visible

    // ---- load A fragments ONCE (register-resident: 2 splits x 8 chunks x 4)
    uint32_t aF[2][8][4];
    {
        uint32_t row = (uint32_t)(wx * 16) + (uint32_t)(l & 15);
        uint32_t kbl = (uint32_t)((l >> 4) & 1) * 16u;
        uint32_t base = sb + SM_AB + row * ROW_PITCH + kbl;
#pragma unroll
        for (int s = 0; s < 2; s++)
#pragma unroll
            for (int c = 0; c < 8; c++)
                ldsm4(aF[s][c], base + (uint32_t)s * A_SPLIT + (uint32_t)c * 32u);
    }
    float lqr[2];
    lqr[0] = l2q_s[wx * 16 + lq];
    lqr[1] = l2q_s[wx * 16 + lq + 8];
    __syncthreads();     // A image consumed -> buf0 free for B

    // first B tile into buf0 (overwrites A image)
    load_b(sb, 0, 0, tid);
    cp_commit();

    // B lane base; buf offset added per tile
    uint32_t bBase;
    {
        uint32_t row = (uint32_t)(wy * 32) + (uint32_t)(l & 7) + (uint32_t)((l >> 4) & 1) * 8u;
        uint32_t kbl = (uint32_t)((l >> 3) & 1) * 16u;
        bBase = sb + SM_AB + row * ROW_PITCH + kbl;
    }

    unsigned long long t1[2] = {U64MAX, U64MAX};
    unsigned long long t2[2] = {U64MAX, U64MAX};

    for (int nt = 0; nt < NUM_NT; nt++) {
        cp_wait0();          // tile nt arrived (only group in flight)
        __syncthreads();     // visible to all; all warps done with other buf
        if (nt + 1 < NUM_NT) {
            load_b(sb, (nt + 1) & 1, nt + 1, tid);
            cp_commit();
        }

        float acc[4][4];
#pragma unroll
        for (int n8 = 0; n8 < 4; n8++)
#pragma unroll
            for (int q = 0; q < 4; q++) acc[n8][q] = 0.f;

        const uint32_t bOff = (uint32_t)(nt & 1) * B_BUF;

#pragma unroll
        for (int c = 0; c < 8; c++) {
            const uint32_t kb = (uint32_t)c * 32u;
            uint32_t bF[2][2][4];    // [split][ni16][reg]
#pragma unroll
            for (int s = 0; s < 2; s++)
#pragma unroll
                for (int g = 0; g < 2; g++)
                    ldsm4(bF[s][g],
                          bBase + bOff + (uint32_t)s * B_SPLIT
                                + (uint32_t)g * (16u * ROW_PITCH) + kb);

            // passes: hh, hM, mH
            const int PA[3] = {0, 0, 1};
            const int PB[3] = {0, 1, 0};
#pragma unroll
            for (int p = 0; p < 3; p++)
#pragma unroll
                for (int n8 = 0; n8 < 4; n8++)
                    mma_f16(acc[n8], aF[PA[p]][c], &bF[PB[p]][n8 >> 1][(n8 & 1) * 2]);
        }

        // epilogue: branchless packed top-2 (ascending index order)
#pragma unroll
        for (int n8 = 0; n8 < 4; n8++) {
            const int col0 = nt * 64 + wy * 32 + n8 * 8 + (lr << 1);
            const float2 lk = *(const float2*)(l2k_s + col0);
            float v;
            v = __fmaf_rn(-2.f, acc[n8][0], __fadd_rn(lqr[0], lk.x));
            t2upd(t1[0], t2[0], v, (unsigned)col0);
            v = __fmaf_rn(-2.f, acc[n8][1], __fadd_rn(lqr[0], lk.y));
            t2upd(t1[0], t2[0], v, (unsigned)(col0 + 1));
            v = __fmaf_rn(-2.f, acc[n8][2], __fadd_rn(lqr[1], lk.x));
            t2upd(t1[1], t2[1], v, (unsigned)col0);
            v = __fmaf_rn(-2.f, acc[n8][3], __fadd_rn(lqr[1], lk.y));
            t2upd(t1[1], t2[1], v, (unsigned)(col0 + 1));
        }
        // no trailing barrier: next iteration's barrier protects buffer reuse
    }

    // ---- merge top-2 across the 4 lanes (lr) sharing each row
#pragma unroll
    for (int h = 0; h < 2; h++) {
        unsigned long long b1 = t1[h], b2 = t2[h];
#pragma unroll
        for (int off = 1; off <= 2; off <<= 1) {
            unsigned long long o1 = shfl_xor_u64(b1, off);
            unsigned long long o2 = shfl_xor_u64(b2, off);
            unsigned long long mx = b1 > o1 ? b1 : o1;
            b1 = b1 < o1 ? b1 : o1;
            unsigned long long mn2 = b2 < o2 ? b2 : o2;
            b2 = mn2 < mx ? mn2 : mx;
        }
        if (lr == 0) {
            int row = wx * 16 + h * 8 + lq;
            cand[row * 4 + wy * 2 + 0] = b1;
            cand[row * 4 + wy * 2 + 1] = b2;
        }
    }
    __syncthreads();

    // ---- per-row final scan + rare exact refine
    if (tid < 64) {
        unsigned long long b1 = U64MAX, b2 = U64MAX;
#pragma unroll
        for (int j = 0; j < 4; j++) {
            unsigned long long p = cand[tid * 4 + j];
            unsigned long long mx = p > b1 ? p : b1;
            b1 = p < b1 ? p : b1;
            b2 = mx < b2 ? mx : b2;
        }
        float v1 = __uint_as_float((uint32_t)(b1 >> 32));
        float v2 = __uint_as_float((uint32_t)(b2 >> 32));
        int best = (int)(uint32_t)(b1 & 0xFFFFFFFFu);
        if (v2 - v1 <= THRESH) {
            const float* xrow = x + (size_t)(m0 + tid) * D_DIM;
            const float l2q_r = l2q_s[tid];
            float bd = 3.0e38f;
            int   bi = 0x7fffffff;
#pragma unroll
            for (int j = 0; j < 4; j++) {
                unsigned long long p = cand[tid * 4 + j];
                float pv = __uint_as_float((uint32_t)(p >> 32));
                if (pv <= v1 + THRESH) {
                    int n = (int)(uint32_t)(p & 0xFFFFFFFFu);
                    float d = exact_dist(xrow, w, n, l2q_r, l2k_s[n]);
                    if (d < bd || (d == bd && n < bi)) { bd = d; bi = n; }
                }
            }
            best = bi;
        }
        best_s[tid] = best;
        atomicAdd(&g_counts[best], 1);
        out[IDX_OFF + m0 + tid] = (float)best;
    }
    __syncthreads();

    // ---- gather z, quantized_st = x + (z - x), loss partial (quarter-row/thread)
    {
        const int r  = tid >> 2;
        const int kb = (tid & 3) << 5;
        const int best = best_s[r];
        const float4* xr = (const float4*)(x + (size_t)(m0 + r) * D_DIM + kb);
        const float4* wz = (const float4*)(w + (size_t)best * D_DIM + kb);
        float4* oq = (float4*)(out + (size_t)(m0 + r) * D_DIM + kb);
        float lsum = 0.f;
#pragma unroll
        for (int i = 0; i < 8; i++) {
            float4 xv = xr[i], z = wz[i];
            float4 qv;
            qv.x = __fadd_rn(xv.x, __fsub_rn(z.x, xv.x));
            qv.y = __fadd_rn(xv.y, __fsub_rn(z.y, xv.y));
            qv.z = __fadd_rn(xv.z, __fsub_rn(z.z, xv.z));
            qv.w = __fadd_rn(xv.w, __fsub_rn(z.w, xv.w));
            oq[i] = qv;
            float d0 = __fsub_rn(qv.x, xv.x), d1 = __fsub_rn(qv.y, xv.y);
            float d2 = __fsub_rn(qv.z, xv.z), d3 = __fsub_rn(qv.w, xv.w);
            lsum += d0 * d0 + d1 * d1 + d2 * d2 + d3 * d3;
        }
#pragma unroll
        for (int o = 16; o > 0; o >>= 1)
            lsum += __shfl_down_sync(0xffffffffu, lsum, o);
        if ((tid & 31) == 0) wsum[wid] = lsum;
    }
    __syncthreads();
    if (tid == 0) {
        float s = 0.f;
#pragma unroll
        for (int i = 0; i < 8; i++) s += wsum[i];
        atomicAdd(&g_loss, s);
    }
}

// ---------------------------------------------------------------------------
// finalize: loss mean + perplexity
// ---------------------------------------------------------------------------
__global__ void finalize_kernel(float* __restrict__ out) {
    int t = threadIdx.x;
    float s = 0.f;
    for (int i = t; i < M_CB; i += 256) {
        float p = (float)g_counts[i] * (1.0f / 65536.0f);
        s += p * logf(p + 1e-10f);
    }
#pragma unroll
    for (int o = 16; o > 0; o >>= 1)
        s += __shfl_down_sync(0xffffffffu, s, o);
    __shared__ float ws[8];
    if ((t & 31) == 0) ws[t >> 5] = s;
    __syncthreads();
    if (t == 0) {
        float tot = 0.f;
#pragma unroll
        for (int i = 0; i < 8; i++) tot += ws[i];
        out[LOSS_OFF] = g_loss * (1.0f / 8388608.0f);
        out[PERP_OFF] = expf(-tot);
    }
}

// ---------------------------------------------------------------------------
extern "C" void kernel_launch(void* const* d_in, const int* in_sizes, int n_in,
                              void* d_out, int out_size) {
    const float* x = (const float*)d_in[0];
    const float* w = (const float*)d_in[1];
    if (n_in >= 2 && in_sizes[0] == M_CB * D_DIM && in_sizes[1] == Q_ELEMS) {
        x = (const float*)d_in[1];
        w = (const float*)d_in[0];
    }
    float* out = (float*)d_out;

    cudaFuncSetAttribute(vq_main_kernel,
                         cudaFuncAttributeMaxDynamicSharedMemorySize, SM_TOTAL);

    // same launch order that successfully profiled vq_main last rounds
    prep_kernel<<<128, 256>>>(w);
    noop_kernel<<<1, 1>>>();
    noop_kernel<<<1, 1>>>();
    vq_main_kernel<<<BN_TOTAL / 64, 256, SM_TOTAL>>>(x, w, out);
    finalize_kernel<<<1, 256>>>(out);
}